// round 15
// baseline (speedup 1.0000x reference)
#include <cuda_runtime.h>
#include <cuda_bf16.h>
#include <cstdint>

#define BATCH 4096
#define SEQ   19
#define EDIM  128
#define HDIM  1920
#define G4    7680
#define KTOT  2176
#define NTOK2 20

#define BK      64                   /* bf16 elems per K-block: 128B rows */
#define NIT     (KTOT / BK)          /* 34 */
#define ASTG_B  (128 * BK * 2)       /* 16384 */
#define BSTG_B  (128 * BK * 2)       /* 16384 */
#define STG_B   (ASTG_B + BSTG_B)    /* 32768 */
#define SMEM_BYTES (STG_B * 3)       /* 98304 */

#define MT   32                      /* m-groups (128 rows each) */
#define JT   60                      /* j-tiles (32 channels each) */
#define TPS  (MT * JT)               /* tiles per step = 1920 */
#define TOT  (SEQ * TPS)

// ---------------- device scratch (static, no allocation) ----------------
__device__ __nv_bfloat16 g_W [(size_t)G4 * KTOT];          // [7680][2176] = [W_ih | W_hh] bf16
__device__ __nv_bfloat16 g_X [(size_t)SEQ * BATCH * 256];  // per-step inputs [t][b][256]
__device__ __nv_bfloat16 g_H0[(size_t)BATCH * HDIM];       // h ping
__device__ __nv_bfloat16 g_H1[(size_t)BATCH * HDIM];       // h pong
__device__ float         g_C [(size_t)BATCH * HDIM];       // c state fp32
__device__ int           g_cnt[SEQ * MT];                  // per (t, m-group) completion
__device__ int           g_ticket;

// ---------------- helpers ----------------
__device__ __forceinline__ uint32_t smem_u32(const void* p) {
    uint32_t a;
    asm("{ .reg .u64 t; cvta.to.shared.u64 t, %1; cvt.u32.u64 %0, t; }" : "=r"(a) : "l"(p));
    return a;
}
__device__ __forceinline__ void cp16(uint32_t saddr, const void* gaddr) {
    asm volatile("cp.async.cg.shared.global [%0], [%1], 16;" :: "r"(saddr), "l"(gaddr));
}
__device__ __forceinline__ uint32_t sw128(uint32_t off) { return off ^ ((off >> 3) & 0x70); }

__device__ __forceinline__ void ldsm_x4(uint32_t* r, uint32_t addr) {
    asm volatile("ldmatrix.sync.aligned.m8n8.x4.shared.b16 {%0,%1,%2,%3}, [%4];"
                 : "=r"(r[0]), "=r"(r[1]), "=r"(r[2]), "=r"(r[3]) : "r"(addr));
}
__device__ __forceinline__ void mma16816(float* c, const uint32_t* a, const uint32_t* b) {
    asm volatile("mma.sync.aligned.m16n8k16.row.col.f32.bf16.bf16.f32 "
                 "{%0,%1,%2,%3}, {%4,%5,%6,%7}, {%8,%9}, {%0,%1,%2,%3};"
                 : "+f"(c[0]), "+f"(c[1]), "+f"(c[2]), "+f"(c[3])
                 : "r"(a[0]), "r"(a[1]), "r"(a[2]), "r"(a[3]), "r"(b[0]), "r"(b[1]));
}
__device__ __forceinline__ int ld_acq(const int* p) {
    int v;
    asm volatile("ld.acquire.gpu.global.s32 %0, [%1];" : "=r"(v) : "l"(p));
    return v;
}
__device__ __forceinline__ float tanh_fa(float x) {
    float y;
    asm("tanh.approx.f32 %0, %1;" : "=f"(y) : "f"(x));
    return y;
}
__device__ __forceinline__ float sigm_fa(float x) {
    return fmaf(tanh_fa(0.5f * x), 0.5f, 0.5f);
}

// ---------------- prep kernels ----------------
__global__ void k_prep_w(const float* __restrict__ Wih, const float* __restrict__ Whh) {
    size_t n = (size_t)G4 * KTOT;
    for (size_t i = (size_t)blockIdx.x * blockDim.x + threadIdx.x; i < n;
         i += (size_t)gridDim.x * blockDim.x) {
        size_t r = i / KTOT; int k = (int)(i % KTOT);
        float v = (k < 256) ? Wih[r * 256 + k] : Whh[r * HDIM + (k - 256)];
        g_W[i] = __float2bfloat16(v);
    }
}
__global__ void k_prep_x(const int* __restrict__ in1, const float* __restrict__ emb,
                         const float* __restrict__ pos) {
    size_t n = (size_t)SEQ * BATCH * 256;
    for (size_t i = (size_t)blockIdx.x * blockDim.x + threadIdx.x; i < n;
         i += (size_t)gridDim.x * blockDim.x) {
        int e = (int)(i & 255);
        size_t bt = i >> 8;
        int b = (int)(bt & (BATCH - 1));
        int t = (int)(bt >> 12);
        float v = (e < 128) ? emb[(size_t)in1[b * SEQ + t] * EDIM + e]
                            : pos[t * EDIM + (e - 128)];
        g_X[i] = __float2bfloat16(v);
    }
}
__global__ void k_init() {
    size_t n = (size_t)BATCH * HDIM;
    size_t nh = n / 2;
    size_t gid0 = (size_t)blockIdx.x * blockDim.x + threadIdx.x;
    for (size_t i = gid0; i < n; i += (size_t)gridDim.x * blockDim.x) {
        g_C[i] = 0.f;
        if (i < nh) {
            ((uint32_t*)g_H0)[i] = 0u;
            ((uint32_t*)g_H1)[i] = 0u;
        }
        if (i < SEQ * MT) g_cnt[i] = 0;
    }
    if (gid0 == 0) g_ticket = 0;
}

// ---------------- persistent LSTM: 3-stage pipeline, 1 barrier/iter ----------------
// CTA: 256 threads = 8 warps. Tile M128 x N128 (4 gates x 32 ch).
// Warp tile M64 (wm half) x N32 (wn 8-ch slice x 4 gates, gate-fused).
// Stage s lives in buffer s%3. Iter it: wait_group 1 -> bar -> issue it+2 -> compute it.
__global__ void __launch_bounds__(256, 2)
k_lstm(const float* __restrict__ b_ih, const float* __restrict__ b_hh) {
    extern __shared__ __align__(128) char smem[];
    __shared__ int s_tk;
    uint32_t sb = smem_u32(smem);
    int tid = threadIdx.x, lane = tid & 31, wid = tid >> 5;
    int wm = wid >> 2;          // 0..1 (M half)
    int wn = wid & 3;           // 0..3 (8-channel slice)
    int r0 = tid >> 3, ch = tid & 7;   // loader coords: r0 0..31, ch 0..7

    // tile-invariant ldsm offsets (within stage)
    uint32_t af_b[4], bf_b[2];
    #pragma unroll
    for (int mt = 0; mt < 4; mt++)
        af_b[mt] = sw128((uint32_t)((wm * 64 + mt * 16 + (lane & 15)) * 128
                                    + ((lane >> 4) * 16)));
    #pragma unroll
    for (int gp = 0; gp < 2; gp++) {
        int nrow = gp * 64 + (((lane >> 4) & 1) * 32) + wn * 8 + (lane & 7);
        bf_b[gp] = (uint32_t)ASTG_B
                 + sw128((uint32_t)(nrow * 128 + (((lane >> 3) & 1) * 16)));
    }
    // loader smem offset (rows r0+32i -> +4096B per i, swizzle-invariant)
    uint32_t aoff0 = sw128((uint32_t)(r0 * 128 + ch * 16));
    // W chunk byte offsets (rows r0+32i of the 128-row gate-block)
    uint32_t woff[4];
    #pragma unroll
    for (int i = 0; i < 4; i++) {
        int nrow = r0 + 32 * i;
        int g = nrow >> 5, c = nrow & 31;
        woff[i] = (uint32_t)(((size_t)g * HDIM + c) * KTOT * 2 + ch * 16);
    }
    int lq = lane & 3, lr = lane >> 2;

    // stage 0 of tile tk2 is x + W only (k0 = (tk2&3)*BK <= 192 < 256): dep-free
    auto issue_stage0 = [&](int tk2) {
        int t2   = tk2 / TPS;
        int rem2 = tk2 - t2 * TPS;
        int m02  = (rem2 / JT) * 128;
        int j02  = (rem2 - (rem2 / JT) * JT) * 32;
        int k0   = (tk2 & 3) * BK;
        const char* xb = (const char*)(g_X + ((size_t)t2 * BATCH + m02) * 256
                                       + (size_t)r0 * 256 + ch * 8) + (size_t)k0 * 2;
        #pragma unroll
        for (int i = 0; i < 4; i++)
            cp16(sb + aoff0 + (uint32_t)(i * 4096), xb + (size_t)i * 16384);
        const char* wb = (const char*)(g_W + (size_t)j02 * KTOT) + (size_t)k0 * 2;
        uint32_t bB = sb + ASTG_B + aoff0;
        #pragma unroll
        for (int i = 0; i < 4; i++)
            cp16(bB + (uint32_t)(i * 4096), wb + woff[i]);
    };

    if (tid == 0) s_tk = atomicAdd(&g_ticket, 1);
    __syncthreads();
    int tk = s_tk;
    if (tk < TOT) {
        issue_stage0(tk);
        asm volatile("cp.async.commit_group;" ::: "memory");
    }

    while (tk < TOT) {
        int t   = tk / TPS;
        int rem = tk - t * TPS;
        int mi  = rem / JT;
        int jj  = rem - mi * JT;
        int m0 = mi * 128, j0 = jj * 32;
        int koff = tk & 3;

        // dependency: all 60 j-tiles of (t-1, mi) complete (h RAW + ping-pong WAR + c)
        if (t > 0) {
            if (tid == 0) {
                const int* cp = &g_cnt[(t - 1) * MT + mi];
                while (ld_acq(cp) < JT) __nanosleep(32);
            }
            __syncthreads();
        }

        const __nv_bfloat16* hsrc = (t & 1) ? g_H1 : g_H0;
        __nv_bfloat16*       hdst = (t & 1) ? g_H0 : g_H1;
        const char* axp0 = (const char*)(g_X + ((size_t)t * BATCH + m0) * 256
                                         + (size_t)r0 * 256 + ch * 8);          // +16384*i
        const char* ahp0 = (const char*)(hsrc + (size_t)m0 * HDIM
                                         + (size_t)r0 * HDIM + ch * 8);         // +122880*i
        const char* wj = (const char*)(g_W + (size_t)j0 * KTOT);

        float acc[4][4][4];
        #pragma unroll
        for (int a = 0; a < 4; a++)
            #pragma unroll
            for (int b = 0; b < 4; b++)
                #pragma unroll
                for (int d = 0; d < 4; d++) acc[a][b][d] = 0.f;

        auto kof = [&](int it) {
            int k = it + koff;
            if (k >= NIT) k -= NIT;
            return k * BK;
        };
        auto issue_loads = [&](uint32_t stgB, int k0) {
            size_t kb = (size_t)k0 * 2;
            bool useH = (k0 >= 256);
            size_t kbh = (size_t)(k0 - 256) * 2;
            #pragma unroll
            for (int i = 0; i < 4; i++) {
                const char* ap = useH ? (ahp0 + kbh + (size_t)i * 122880)
                                      : (axp0 + kb + (size_t)i * 16384);
                cp16(stgB + aoff0 + (uint32_t)(i * 4096), ap);
            }
            uint32_t bB = stgB + ASTG_B + aoff0;
            #pragma unroll
            for (int i = 0; i < 4; i++)
                cp16(bB + (uint32_t)(i * 4096), wj + woff[i] + kb);
        };

        // stage 0 already in flight (prefetched); issue stage 1 (may be h: after dep wait)
        issue_loads(sb + STG_B, kof(1));
        asm volatile("cp.async.commit_group;" ::: "memory");

        uint32_t compB  = sb;                 // buffer of stage it   (it%3)
        uint32_t issueB = sb + 2 * STG_B;     // buffer of stage it+2 ((it+2)%3)
        const uint32_t sEnd = sb + 3 * STG_B;

        #pragma unroll 2
        for (int it = 0; it < NIT; it++) {
            // outstanding groups: stages it, it+1 (+ empties) -> stage it completes
            asm volatile("cp.async.wait_group 1;" ::: "memory");
            // bar: (a) stage it visible to all warps, (b) all warps finished
            // compute(it-1), so buffer (it+2)%3 == (it-1)%3 is free for reuse
            __syncthreads();
            int pf = it + 2;
            if (pf < NIT) issue_loads(issueB, kof(pf));
            asm volatile("cp.async.commit_group;" ::: "memory");   // empty group ok

            #pragma unroll
            for (int kk = 0; kk < 4; kk++) {
                uint32_t kx = (uint32_t)(kk * 32);
                uint32_t af[4][4];
                #pragma unroll
                for (int mt = 0; mt < 4; mt++) ldsm_x4(af[mt], compB + (af_b[mt] ^ kx));
                #pragma unroll
                for (int gp = 0; gp < 2; gp++) {
                    uint32_t bf[4];
                    ldsm_x4(bf, compB + (bf_b[gp] ^ kx));
                    #pragma unroll
                    for (int mt = 0; mt < 4; mt++) {
                        mma16816(acc[mt][2 * gp + 0], af[mt], &bf[0]);
                        mma16816(acc[mt][2 * gp + 1], af[mt], &bf[2]);
                    }
                }
            }
            compB += STG_B;  if (compB  == sEnd) compB  = sb;
            issueB += STG_B; if (issueB == sEnd) issueB = sb;
        }

        // all warps past last compute -> buffer 0 free; grab + prefetch next tile
        __syncthreads();
        if (tid == 0) s_tk = atomicAdd(&g_ticket, 1);
        __syncthreads();
        int ntk = s_tk;
        if (ntk < TOT) {
            issue_stage0(ntk);     // x + W only: no dependency needed
            asm volatile("cp.async.commit_group;" ::: "memory");
        }

        // ---- fused LSTM cell epilogue (tanh.approx; L2-coherent c) ----
        float bias[4][2];
        #pragma unroll
        for (int g = 0; g < 4; g++)
            #pragma unroll
            for (int cc = 0; cc < 2; cc++) {
                int j = g * HDIM + j0 + wn * 8 + lq * 2 + cc;
                bias[g][cc] = b_ih[j] + b_hh[j];
            }

        #pragma unroll
        for (int mt = 0; mt < 4; mt++)
            #pragma unroll
            for (int rh = 0; rh < 2; rh++) {
                int row = m0 + wm * 64 + mt * 16 + lr + rh * 8;
                size_t base = (size_t)row * HDIM + j0;
                int chn = wn * 8 + lq * 2;
                float2 cold = __ldcg((const float2*)(g_C + base + chn));
                float cn[2], hn[2];
                #pragma unroll
                for (int cc = 0; cc < 2; cc++) {
                    int fi = rh * 2 + cc;
                    float iv = sigm_fa(acc[mt][0][fi] + bias[0][cc]);
                    float fv = sigm_fa(acc[mt][1][fi] + bias[1][cc]);
                    float gv = tanh_fa(acc[mt][2][fi] + bias[2][cc]);
                    float ov = sigm_fa(acc[mt][3][fi] + bias[3][cc]);
                    float co = cc ? cold.y : cold.x;
                    cn[cc] = fv * co + iv * gv;
                    hn[cc] = ov * tanh_fa(cn[cc]);
                }
                __stcg((float2*)(g_C + base + chn), make_float2(cn[0], cn[1]));
                __nv_bfloat162 hv;
                hv.x = __float2bfloat16(hn[0]);
                hv.y = __float2bfloat16(hn[1]);
                *(__nv_bfloat162*)(hdst + base + chn) = hv;
            }

        __syncthreads();           // all threads' h/c writes issued
        if (tid == 0) {
            __threadfence();       // publish h/c before counting
            atomicAdd(&g_cnt[t * MT + mi], 1);
        }
        tk = ntk;
    }
}

// ---------------- final: windowed einsum + max + log-softmax ----------------
__global__ void k_final(const int* __restrict__ in2, const float* __restrict__ emb,
                        const float* __restrict__ lw, const float* __restrict__ lb,
                        float* __restrict__ out) {
    int b = blockIdx.x;
    __shared__ __align__(16) float se[NTOK2 * 128];
    __shared__ __align__(16) float shv[HDIM];
    __shared__ float sd[300];
    __shared__ float sred[4];
    int tid = threadIdx.x;  // 128 threads

    for (int i = tid; i < NTOK2 * 128; i += 128) {
        int n = i >> 7, e = i & 127;
        se[i] = emb[(size_t)in2[b * NTOK2 + n] * EDIM + e];
    }
    for (int i = tid; i < HDIM; i += 128)
        shv[i] = __bfloat162float(g_H1[(size_t)b * HDIM + i]);
    __syncthreads();

    for (int p = tid; p < 300; p += 128) {       // dotE[m][tok], m<15, tok<20
        int m = p / 20, n = p % 20;
        const float4* hv = (const float4*)(shv + m * 128);
        const float4* ev = (const float4*)(se + n * 128);
        float accv = 0.f;
        #pragma unroll
        for (int e = 0; e < 32; e++) {
            float4 a = hv[e], c = ev[e];
            accv = fmaf(a.x, c.x, fmaf(a.y, c.y, fmaf(a.z, c.z, fmaf(a.w, c.w, accv))));
        }
        sd[p] = accv;
    }
    __syncthreads();

    float mx = -3.4e38f;
    for (int p = tid; p < 90; p += 128) {
        int k = p / 18, n = p % 18;
        float rs = sd[(3 * k) * 20 + n] + sd[(3 * k + 1) * 20 + n + 1]
                 + sd[(3 * k + 2) * 20 + n + 2];
        mx = fmaxf(mx, rs);
    }
    #pragma unroll
    for (int o = 16; o > 0; o >>= 1) mx = fmaxf(mx, __shfl_xor_sync(0xffffffffu, mx, o));
    if ((tid & 31) == 0) sred[tid >> 5] = mx;
    __syncthreads();
    if (tid == 0) {
        float ms = fmaxf(fmaxf(sred[0], sred[1]), fmaxf(sred[2], sred[3]));
        float l0 = ms * lw[0] + lb[0];
        float l1 = ms * lw[1] + lb[1];
        float m2 = fmaxf(l0, l1);
        float lse = m2 + logf(expf(l0 - m2) + expf(l1 - m2));
        out[b * 2 + 0] = l0 - lse;
        out[b * 2 + 1] = l1 - lse;
    }
}

// ---------------- launch ----------------
extern "C" void kernel_launch(void* const* d_in, const int* in_sizes, int n_in,
                              void* d_out, int out_size) {
    (void)in_sizes; (void)n_in; (void)out_size;
    const int*   input1 = (const int*)  d_in[0];
    const int*   input2 = (const int*)  d_in[1];
    const float* emb    = (const float*)d_in[2];
    const float* pos    = (const float*)d_in[3];
    const float* W_ih   = (const float*)d_in[4];
    const float* W_hh   = (const float*)d_in[5];
    const float* b_ih   = (const float*)d_in[6];
    const float* b_hh   = (const float*)d_in[7];
    const float* lin_w  = (const float*)d_in[8];
    const float* lin_b  = (const float*)d_in[9];
    float* out = (float*)d_out;

    cudaFuncSetAttribute(k_lstm, cudaFuncAttributeMaxDynamicSharedMemorySize, SMEM_BYTES);

    k_prep_w<<<2048, 256>>>(W_ih, W_hh);
    k_prep_x<<<2048, 256>>>(input1, emb, pos);
    k_init<<<2048, 256>>>();

    // persistent grid: 2 CTAs/SM on 152 SMs; extras exit instantly via ticket bound
    k_lstm<<<304, 256, SMEM_BYTES>>>(b_ih, b_hh);

    k_final<<<BATCH, 128>>>(input2, emb, lin_w, lin_b, out);
}

// round 16
// speedup vs baseline: 1.0301x; 1.0301x over previous
#include <cuda_runtime.h>
#include <cuda_bf16.h>
#include <cstdint>

#define BATCH 4096
#define SEQ   19
#define EDIM  128
#define HDIM  1920
#define G4    7680
#define KTOT  2176
#define NTOK2 20

#define BK      64                   /* bf16 elems per K-block: 128B rows */
#define NIT     (KTOT / BK)          /* 34 */
#define ASTG_B  (64 * BK * 2)        /* 8192  */
#define BSTG_B  (128 * BK * 2)       /* 16384 */
#define STG_B   (ASTG_B + BSTG_B)    /* 24576 */
#define CBUF_OFF (STG_B * 2)         /* 49152: c staging buffer (8192 B) */
#define SMEM_BYTES (CBUF_OFF + 8192) /* 57344 */

#define MT   64                      /* m-groups (64 rows each) */
#define JT   60                      /* j-tiles (32 channels each) */
#define TPS  (MT * JT)               /* tiles per step = 3840 */
#define TOT  (SEQ * TPS)

// ---------------- device scratch (static, no allocation) ----------------
__device__ __nv_bfloat16 g_W [(size_t)G4 * KTOT];          // [7680][2176] = [W_ih | W_hh] bf16
__device__ __nv_bfloat16 g_X [(size_t)SEQ * BATCH * 256];  // per-step inputs [t][b][256]
__device__ __nv_bfloat16 g_H0[(size_t)BATCH * HDIM];       // h ping
__device__ __nv_bfloat16 g_H1[(size_t)BATCH * HDIM];       // h pong
__device__ float         g_C [(size_t)BATCH * HDIM];       // c state fp32
__device__ float         g_B [G4];                         // b_ih + b_hh
__device__ int           g_cnt[SEQ * MT];                  // per (t, m-group) completion
__device__ int           g_ticket;

// ---------------- helpers ----------------
__device__ __forceinline__ uint32_t smem_u32(const void* p) {
    uint32_t a;
    asm("{ .reg .u64 t; cvta.to.shared.u64 t, %1; cvt.u32.u64 %0, t; }" : "=r"(a) : "l"(p));
    return a;
}
__device__ __forceinline__ void cp16(uint32_t saddr, const void* gaddr) {
    asm volatile("cp.async.cg.shared.global [%0], [%1], 16;" :: "r"(saddr), "l"(gaddr));
}
__device__ __forceinline__ uint32_t sw128(uint32_t off) { return off ^ ((off >> 3) & 0x70); }

__device__ __forceinline__ void ldsm_x4(uint32_t* r, uint32_t addr) {
    asm volatile("ldmatrix.sync.aligned.m8n8.x4.shared.b16 {%0,%1,%2,%3}, [%4];"
                 : "=r"(r[0]), "=r"(r[1]), "=r"(r[2]), "=r"(r[3]) : "r"(addr));
}
__device__ __forceinline__ void mma16816(float* c, const uint32_t* a, const uint32_t* b) {
    asm volatile("mma.sync.aligned.m16n8k16.row.col.f32.bf16.bf16.f32 "
                 "{%0,%1,%2,%3}, {%4,%5,%6,%7}, {%8,%9}, {%0,%1,%2,%3};"
                 : "+f"(c[0]), "+f"(c[1]), "+f"(c[2]), "+f"(c[3])
                 : "r"(a[0]), "r"(a[1]), "r"(a[2]), "r"(a[3]), "r"(b[0]), "r"(b[1]));
}
__device__ __forceinline__ int ld_acq(const int* p) {
    int v;
    asm volatile("ld.acquire.gpu.global.s32 %0, [%1];" : "=r"(v) : "l"(p));
    return v;
}
__device__ __forceinline__ float tanh_fa(float x) {
    float y;
    asm("tanh.approx.f32 %0, %1;" : "=f"(y) : "f"(x));
    return y;
}
__device__ __forceinline__ float sigm_fa(float x) {
    return fmaf(tanh_fa(0.5f * x), 0.5f, 0.5f);
}

// ---------------- prep kernels ----------------
__global__ void k_prep_w(const float* __restrict__ Wih, const float* __restrict__ Whh) {
    size_t n = (size_t)G4 * KTOT;
    for (size_t i = (size_t)blockIdx.x * blockDim.x + threadIdx.x; i < n;
         i += (size_t)gridDim.x * blockDim.x) {
        size_t r = i / KTOT; int k = (int)(i % KTOT);
        float v = (k < 256) ? Wih[r * 256 + k] : Whh[r * HDIM + (k - 256)];
        g_W[i] = __float2bfloat16(v);
    }
}
__global__ void k_prep_x(const int* __restrict__ in1, const float* __restrict__ emb,
                         const float* __restrict__ pos) {
    size_t n = (size_t)SEQ * BATCH * 256;
    for (size_t i = (size_t)blockIdx.x * blockDim.x + threadIdx.x; i < n;
         i += (size_t)gridDim.x * blockDim.x) {
        int e = (int)(i & 255);
        size_t bt = i >> 8;
        int b = (int)(bt & (BATCH - 1));
        int t = (int)(bt >> 12);
        float v = (e < 128) ? emb[(size_t)in1[b * SEQ + t] * EDIM + e]
                            : pos[t * EDIM + (e - 128)];
        g_X[i] = __float2bfloat16(v);
    }
}
__global__ void k_init(const float* __restrict__ b_ih, const float* __restrict__ b_hh) {
    size_t n = (size_t)BATCH * HDIM;
    size_t nh = n / 2;
    size_t gid0 = (size_t)blockIdx.x * blockDim.x + threadIdx.x;
    for (size_t i = gid0; i < n; i += (size_t)gridDim.x * blockDim.x) {
        g_C[i] = 0.f;
        if (i < nh) {
            ((uint32_t*)g_H0)[i] = 0u;
            ((uint32_t*)g_H1)[i] = 0u;
        }
        if (i < SEQ * MT) g_cnt[i] = 0;
        if (i < G4) g_B[i] = b_ih[i] + b_hh[i];
    }
    if (gid0 == 0) g_ticket = 0;
}

// ---------------- persistent LSTM: all 19 steps, ticketed tiles ----------------
// CTA: 128 threads = 4 warps. Tile M64 x N128 (4 gates x 32 ch), warp M64xN32 gate-fused.
// Stage 0 of every tile is an x-chunk (koff = tk&3) -> dependency-free; the NEXT
// tile's stage 0 is prefetched during the CURRENT tile's epilogue. The c tile is
// staged through smem (CBUF) via its own cp.async group issued after the dep wait.
__global__ void __launch_bounds__(128, 4)
k_lstm() {
    extern __shared__ __align__(128) char smem[];
    __shared__ int s_tk;
    uint32_t sb = smem_u32(smem);
    int tid = threadIdx.x, lane = tid & 31;
    int wn = tid >> 5;
    int r0 = tid >> 3, ch = tid & 7;

    // tile-invariant ldsm offsets (within stage)
    uint32_t af_b[4], bf_b[2];
    #pragma unroll
    for (int mt = 0; mt < 4; mt++)
        af_b[mt] = sw128((uint32_t)((mt * 16 + (lane & 15)) * 128
                                    + ((lane >> 4) * 16)));
    #pragma unroll
    for (int gp = 0; gp < 2; gp++) {
        int nrow = gp * 64 + (((lane >> 4) & 1) * 32) + wn * 8 + (lane & 7);
        bf_b[gp] = (uint32_t)ASTG_B
                 + sw128((uint32_t)(nrow * 128 + (((lane >> 3) & 1) * 16)));
    }
    uint32_t aoff0 = sw128((uint32_t)(r0 * 128 + ch * 16));
    // W chunk offsets: independent of tile (j0 folded into base pointer)
    uint32_t woff[8];
    #pragma unroll
    for (int i = 0; i < 8; i++) {
        int nrow = r0 + 16 * i;
        int g = nrow >> 5, c = nrow & 31;
        woff[i] = (uint32_t)(((size_t)g * HDIM + c) * KTOT * 2 + ch * 16);
    }
    int lq = lane & 3, lr = lane >> 2;

    // issue stage 0 (x + W only; k0 = q*BK <= 192 < 256) for tile tk2
    auto issue_stage0 = [&](int tk2) {
        int t2   = tk2 / TPS;
        int rem2 = tk2 - t2 * TPS;
        int m02  = (rem2 / JT) * 64;
        int j02  = (rem2 - (rem2 / JT) * JT) * 32;
        int k0   = (tk2 & 3) * BK;
        const char* xb = (const char*)(g_X + ((size_t)t2 * BATCH + m02) * 256
                                       + (size_t)r0 * 256 + ch * 8) + (size_t)k0 * 2;
        #pragma unroll
        for (int i = 0; i < 4; i++)
            cp16(sb + aoff0 + (uint32_t)(i * 2048), xb + (size_t)i * 8192);
        const char* wb = (const char*)(g_W + (size_t)j02 * KTOT) + (size_t)k0 * 2;
        uint32_t bB = sb + ASTG_B + aoff0;
        #pragma unroll
        for (int i = 0; i < 8; i++)
            cp16(bB + (uint32_t)(i * 2048), wb + woff[i]);
    };

    if (tid == 0) s_tk = atomicAdd(&g_ticket, 1);
    __syncthreads();
    int tk = s_tk;
    if (tk < TOT) {
        issue_stage0(tk);
        asm volatile("cp.async.commit_group;" ::: "memory");
    }

    while (tk < TOT) {
        int t   = tk / TPS;
        int rem = tk - t * TPS;
        int mi  = rem / JT;
        int jj  = rem - mi * JT;
        int m0 = mi * 64, j0 = jj * 32;
        int koff = tk & 3;

        // dependency: all 60 j-tiles of (t-1, mi) complete (h RAW + ping-pong WAR + c)
        if (t > 0) {
            if (tid == 0) {
                const int* cp = &g_cnt[(t - 1) * MT + mi];
                while (ld_acq(cp) < JT) __nanosleep(32);
            }
            __syncthreads();
        }

        // stage c tile (64 rows x 32 f32 = 8KB) into CBUF as its own group.
        // Lands during mainloop iter 0's wait_group; read by epilogue via LDS.
        {
            // 512 chunks of 16B: chunk = tid + 128*i -> row = chunk>>3, c8 = chunk&7
            const char* cg = (const char*)(g_C + (size_t)(m0 + r0) * HDIM + j0) + ch * 16;
            #pragma unroll
            for (int i = 0; i < 4; i++)
                cp16(sb + CBUF_OFF + (uint32_t)(r0 * 128 + ch * 16 + i * 2048),
                     cg + (size_t)i * 16 * HDIM * 4);
            asm volatile("cp.async.commit_group;" ::: "memory");
        }

        const __nv_bfloat16* hsrc = (t & 1) ? g_H1 : g_H0;
        __nv_bfloat16*       hdst = (t & 1) ? g_H0 : g_H1;
        const char* axp0 = (const char*)(g_X + ((size_t)t * BATCH + m0) * 256
                                         + (size_t)r0 * 256 + ch * 8);          // +8192*i
        const char* ahp0 = (const char*)(hsrc + (size_t)m0 * HDIM
                                         + (size_t)r0 * HDIM + ch * 8);         // +61440*i
        const char* wj = (const char*)(g_W + (size_t)j0 * KTOT);

        float acc[4][4][4];
        #pragma unroll
        for (int a = 0; a < 4; a++)
            #pragma unroll
            for (int b = 0; b < 4; b++)
                #pragma unroll
                for (int d = 0; d < 4; d++) acc[a][b][d] = 0.f;

        auto kof = [&](int it) {
            int k = it + koff;
            if (k >= NIT) k -= NIT;
            return k * BK;
        };
        auto issue_loads = [&](uint32_t stgB, int k0) {
            size_t kb = (size_t)k0 * 2;
            bool useH = (k0 >= 256);
            size_t kbh = (size_t)(k0 - 256) * 2;
            #pragma unroll
            for (int i = 0; i < 4; i++) {
                const char* ap = useH ? (ahp0 + kbh + (size_t)i * 61440)
                                      : (axp0 + kb + (size_t)i * 8192);
                cp16(stgB + aoff0 + (uint32_t)(i * 2048), ap);
            }
            uint32_t bB = stgB + ASTG_B + aoff0;
            #pragma unroll
            for (int i = 0; i < 8; i++)
                cp16(bB + (uint32_t)(i * 2048), wj + woff[i] + kb);
        };

        // mainloop: stage 0 already in flight (issued during previous epilogue)
        #pragma unroll 2
        for (int it = 0; it < NIT; it++) {
            __syncthreads();
            int pf = it + 1;
            if (pf < NIT) issue_loads(sb + (pf & 1) * STG_B, kof(pf));
            asm volatile("cp.async.commit_group;" ::: "memory");
            asm volatile("cp.async.wait_group 1;" ::: "memory");
            __syncthreads();

            uint32_t aB = sb + (it & 1) * STG_B;
            #pragma unroll
            for (int kk = 0; kk < 4; kk++) {
                uint32_t kx = (uint32_t)(kk * 32);
                uint32_t af[4][4];
                #pragma unroll
                for (int mt = 0; mt < 4; mt++) ldsm_x4(af[mt], aB + (af_b[mt] ^ kx));
                #pragma unroll
                for (int gp = 0; gp < 2; gp++) {
                    uint32_t bf[4];
                    ldsm_x4(bf, aB + (bf_b[gp] ^ kx));
                    #pragma unroll
                    for (int mt = 0; mt < 4; mt++) {
                        mma16816(acc[mt][2 * gp + 0], af[mt], &bf[0]);
                        mma16816(acc[mt][2 * gp + 1], af[mt], &bf[2]);
                    }
                }
            }
        }

        // all warps past iter-33 barrier -> buffer 0 free; grab + prefetch next tile
        __syncthreads();
        if (tid == 0) s_tk = atomicAdd(&g_ticket, 1);
        __syncthreads();
        int ntk = s_tk;
        if (ntk < TOT) {
            issue_stage0(ntk);     // x + W only: no dependency needed
            asm volatile("cp.async.commit_group;" ::: "memory");
        }

        // ---- fused LSTM cell epilogue (tanh.approx; c from smem CBUF) ----
        float bias[4][2];
        #pragma unroll
        for (int g = 0; g < 4; g++)
            #pragma unroll
            for (int cc = 0; cc < 2; cc++)
                bias[g][cc] = g_B[g * HDIM + j0 + wn * 8 + lq * 2 + cc];

        const float* cbuf = (const float*)(smem + CBUF_OFF);
        #pragma unroll
        for (int mt = 0; mt < 4; mt++)
            #pragma unroll
            for (int rh = 0; rh < 2; rh++) {
                int rloc = mt * 16 + lr + rh * 8;
                int row = m0 + rloc;
                size_t base = (size_t)row * HDIM + j0;
                int chn = wn * 8 + lq * 2;
                float2 cold = *(const float2*)(cbuf + rloc * 32 + chn);
                float cn[2], hn[2];
                #pragma unroll
                for (int cc = 0; cc < 2; cc++) {
                    int fi = rh * 2 + cc;
                    float iv = sigm_fa(acc[mt][0][fi] + bias[0][cc]);
                    float fv = sigm_fa(acc[mt][1][fi] + bias[1][cc]);
                    float gv = tanh_fa(acc[mt][2][fi] + bias[2][cc]);
                    float ov = sigm_fa(acc[mt][3][fi] + bias[3][cc]);
                    float co = cc ? cold.y : cold.x;
                    cn[cc] = fv * co + iv * gv;
                    hn[cc] = ov * tanh_fa(cn[cc]);
                }
                __stcg((float2*)(g_C + base + chn), make_float2(cn[0], cn[1]));
                __nv_bfloat162 hv;
                hv.x = __float2bfloat16(hn[0]);
                hv.y = __float2bfloat16(hn[1]);
                *(__nv_bfloat162*)(hdst + base + chn) = hv;
            }

        __syncthreads();           // all threads' h/c writes issued + CBUF reads done
        if (tid == 0) {
            __threadfence();       // publish h/c before counting
            atomicAdd(&g_cnt[t * MT + mi], 1);
        }
        tk = ntk;
    }
}

// ---------------- final: windowed einsum + max + log-softmax ----------------
__global__ void k_final(const int* __restrict__ in2, const float* __restrict__ emb,
                        const float* __restrict__ lw, const float* __restrict__ lb,
                        float* __restrict__ out) {
    int b = blockIdx.x;
    __shared__ __align__(16) float se[NTOK2 * 128];
    __shared__ __align__(16) float shv[HDIM];
    __shared__ float sd[300];
    __shared__ float sred[4];
    int tid = threadIdx.x;  // 128 threads

    for (int i = tid; i < NTOK2 * 128; i += 128) {
        int n = i >> 7, e = i & 127;
        se[i] = emb[(size_t)in2[b * NTOK2 + n] * EDIM + e];
    }
    for (int i = tid; i < HDIM; i += 128)
        shv[i] = __bfloat162float(g_H1[(size_t)b * HDIM + i]);
    __syncthreads();

    for (int p = tid; p < 300; p += 128) {       // dotE[m][tok], m<15, tok<20
        int m = p / 20, n = p % 20;
        const float4* hv = (const float4*)(shv + m * 128);
        const float4* ev = (const float4*)(se + n * 128);
        float accv = 0.f;
        #pragma unroll
        for (int e = 0; e < 32; e++) {
            float4 a = hv[e], c = ev[e];
            accv = fmaf(a.x, c.x, fmaf(a.y, c.y, fmaf(a.z, c.z, fmaf(a.w, c.w, accv))));
        }
        sd[p] = accv;
    }
    __syncthreads();

    float mx = -3.4e38f;
    for (int p = tid; p < 90; p += 128) {
        int k = p / 18, n = p % 18;
        float rs = sd[(3 * k) * 20 + n] + sd[(3 * k + 1) * 20 + n + 1]
                 + sd[(3 * k + 2) * 20 + n + 2];
        mx = fmaxf(mx, rs);
    }
    #pragma unroll
    for (int o = 16; o > 0; o >>= 1) mx = fmaxf(mx, __shfl_xor_sync(0xffffffffu, mx, o));
    if ((tid & 31) == 0) sred[tid >> 5] = mx;
    __syncthreads();
    if (tid == 0) {
        float ms = fmaxf(fmaxf(sred[0], sred[1]), fmaxf(sred[2], sred[3]));
        float l0 = ms * lw[0] + lb[0];
        float l1 = ms * lw[1] + lb[1];
        float m2 = fmaxf(l0, l1);
        float lse = m2 + logf(expf(l0 - m2) + expf(l1 - m2));
        out[b * 2 + 0] = l0 - lse;
        out[b * 2 + 1] = l1 - lse;
    }
}

// ---------------- launch ----------------
extern "C" void kernel_launch(void* const* d_in, const int* in_sizes, int n_in,
                              void* d_out, int out_size) {
    (void)in_sizes; (void)n_in; (void)out_size;
    const int*   input1 = (const int*)  d_in[0];
    const int*   input2 = (const int*)  d_in[1];
    const float* emb    = (const float*)d_in[2];
    const float* pos    = (const float*)d_in[3];
    const float* W_ih   = (const float*)d_in[4];
    const float* W_hh   = (const float*)d_in[5];
    const float* b_ih   = (const float*)d_in[6];
    const float* b_hh   = (const float*)d_in[7];
    const float* lin_w  = (const float*)d_in[8];
    const float* lin_b  = (const float*)d_in[9];
    float* out = (float*)d_out;

    cudaFuncSetAttribute(k_lstm, cudaFuncAttributeMaxDynamicSharedMemorySize, SMEM_BYTES);

    k_prep_w<<<2048, 256>>>(W_ih, W_hh);
    k_prep_x<<<2048, 256>>>(input1, emb, pos);
    k_init<<<2048, 256>>>(b_ih, b_hh);

    // persistent grid: 4 CTAs/SM resident on 148-152 SMs; extras exit instantly
    k_lstm<<<608, 128, SMEM_BYTES>>>();

    k_final<<<BATCH, 128>>>(input2, emb, lin_w, lin_b, out);
}

// round 17
// speedup vs baseline: 1.0918x; 1.0600x over previous
#include <cuda_runtime.h>
#include <cuda_bf16.h>
#include <cstdint>

#define BATCH 4096
#define SEQ   19
#define EDIM  128
#define HDIM  1920
#define G4    7680
#define KTOT  2176
#define NTOK2 20

#define BK      64                   /* bf16 elems per K-block: 128B rows */
#define NIT     (KTOT / BK)          /* 34 */
#define ASTG_B  (64 * BK * 2)        /* 8192  */
#define BSTG_B  (128 * BK * 2)       /* 16384 */
#define STG_B   (ASTG_B + BSTG_B)    /* 24576 */
#define CBUF_OFF (STG_B * 2)         /* 49152: c staging buffer (8192 B) */
#define SMEM_BYTES (CBUF_OFF + 8192) /* 57344 dynamic; no static smem */

#define MT   64                      /* m-groups (64 rows each) */
#define JT   60                      /* j-tiles (32 channels each) */
#define TPS  (MT * JT)               /* tiles per step = 3840 */
#define TOT  (SEQ * TPS)
#define NCTA 608

// ---------------- device scratch (static, no allocation) ----------------
__device__ __nv_bfloat16 g_W [(size_t)G4 * KTOT];          // [7680][2176] = [W_ih | W_hh] bf16
__device__ __nv_bfloat16 g_X [(size_t)SEQ * BATCH * 256];  // per-step inputs [t][b][256]
__device__ __nv_bfloat16 g_H0[(size_t)BATCH * HDIM];       // h ping
__device__ __nv_bfloat16 g_H1[(size_t)BATCH * HDIM];       // h pong
__device__ float         g_C [(size_t)BATCH * HDIM];       // c state fp32
__device__ float         g_B [G4];                         // b_ih + b_hh
__device__ int           g_cnt[SEQ * MT];                  // per (t, m-group) completion
__device__ int           g_ticket;
__device__ int           g_tk[NCTA];                       // per-CTA ticket broadcast

// ---------------- helpers ----------------
__device__ __forceinline__ uint32_t smem_u32(const void* p) {
    uint32_t a;
    asm("{ .reg .u64 t; cvta.to.shared.u64 t, %1; cvt.u32.u64 %0, t; }" : "=r"(a) : "l"(p));
    return a;
}
__device__ __forceinline__ void cp16(uint32_t saddr, const void* gaddr) {
    asm volatile("cp.async.cg.shared.global [%0], [%1], 16;" :: "r"(saddr), "l"(gaddr));
}
__device__ __forceinline__ uint32_t sw128(uint32_t off) { return off ^ ((off >> 3) & 0x70); }

__device__ __forceinline__ void ldsm_x4(uint32_t* r, uint32_t addr) {
    asm volatile("ldmatrix.sync.aligned.m8n8.x4.shared.b16 {%0,%1,%2,%3}, [%4];"
                 : "=r"(r[0]), "=r"(r[1]), "=r"(r[2]), "=r"(r[3]) : "r"(addr));
}
__device__ __forceinline__ void mma16816(float* c, const uint32_t* a, const uint32_t* b) {
    asm volatile("mma.sync.aligned.m16n8k16.row.col.f32.bf16.bf16.f32 "
                 "{%0,%1,%2,%3}, {%4,%5,%6,%7}, {%8,%9}, {%0,%1,%2,%3};"
                 : "+f"(c[0]), "+f"(c[1]), "+f"(c[2]), "+f"(c[3])
                 : "r"(a[0]), "r"(a[1]), "r"(a[2]), "r"(a[3]), "r"(b[0]), "r"(b[1]));
}
__device__ __forceinline__ int ld_acq(const int* p) {
    int v;
    asm volatile("ld.acquire.gpu.global.s32 %0, [%1];" : "=r"(v) : "l"(p));
    return v;
}
__device__ __forceinline__ float tanh_fa(float x) {
    float y;
    asm("tanh.approx.f32 %0, %1;" : "=f"(y) : "f"(x));
    return y;
}
__device__ __forceinline__ float sigm_fa(float x) {
    return fmaf(tanh_fa(0.5f * x), 0.5f, 0.5f);
}

// ---------------- prep kernels ----------------
__global__ void k_prep_w(const float* __restrict__ Wih, const float* __restrict__ Whh) {
    size_t n = (size_t)G4 * KTOT;
    for (size_t i = (size_t)blockIdx.x * blockDim.x + threadIdx.x; i < n;
         i += (size_t)gridDim.x * blockDim.x) {
        size_t r = i / KTOT; int k = (int)(i % KTOT);
        float v = (k < 256) ? Wih[r * 256 + k] : Whh[r * HDIM + (k - 256)];
        g_W[i] = __float2bfloat16(v);
    }
}
__global__ void k_prep_x(const int* __restrict__ in1, const float* __restrict__ emb,
                         const float* __restrict__ pos) {
    size_t n = (size_t)SEQ * BATCH * 256;
    for (size_t i = (size_t)blockIdx.x * blockDim.x + threadIdx.x; i < n;
         i += (size_t)gridDim.x * blockDim.x) {
        int e = (int)(i & 255);
        size_t bt = i >> 8;
        int b = (int)(bt & (BATCH - 1));
        int t = (int)(bt >> 12);
        float v = (e < 128) ? emb[(size_t)in1[b * SEQ + t] * EDIM + e]
                            : pos[t * EDIM + (e - 128)];
        g_X[i] = __float2bfloat16(v);
    }
}
__global__ void k_init(const float* __restrict__ b_ih, const float* __restrict__ b_hh) {
    size_t n = (size_t)BATCH * HDIM;
    size_t nh = n / 2;
    size_t gid0 = (size_t)blockIdx.x * blockDim.x + threadIdx.x;
    for (size_t i = gid0; i < n; i += (size_t)gridDim.x * blockDim.x) {
        g_C[i] = 0.f;
        if (i < nh) {
            ((uint32_t*)g_H0)[i] = 0u;
            ((uint32_t*)g_H1)[i] = 0u;
        }
        if (i < SEQ * MT) g_cnt[i] = 0;
        if (i < G4) g_B[i] = b_ih[i] + b_hh[i];
        if (i < NCTA) g_tk[i] = 0;
    }
    if (gid0 == 0) g_ticket = 0;
}

// ---------------- persistent LSTM: all 19 steps, ticketed tiles ----------------
// CTA: 128 threads = 4 warps. Tile M64 x N128 (4 gates x 32 ch), warp M64xN32 gate-fused.
// Stage 0 of every tile is an x-chunk (koff = tk&3) -> dependency-free; the NEXT
// tile's stage 0 is prefetched during the CURRENT tile's epilogue. The c tile is
// staged through smem (CBUF) via its own cp.async group. Ticket broadcast goes
// through a per-CTA global slot (no static smem -> exact 4-CTA/SM fit).
__global__ void __launch_bounds__(128, 4)
k_lstm() {
    extern __shared__ __align__(128) char smem[];
    uint32_t sb = smem_u32(smem);
    int tid = threadIdx.x, lane = tid & 31;
    int wn = tid >> 5;
    int r0 = tid >> 3, ch = tid & 7;
    int* mytk = &g_tk[blockIdx.x];

    // tile-invariant ldsm offsets (within stage)
    uint32_t af_b[4], bf_b[2];
    #pragma unroll
    for (int mt = 0; mt < 4; mt++)
        af_b[mt] = sw128((uint32_t)((mt * 16 + (lane & 15)) * 128
                                    + ((lane >> 4) * 16)));
    #pragma unroll
    for (int gp = 0; gp < 2; gp++) {
        int nrow = gp * 64 + (((lane >> 4) & 1) * 32) + wn * 8 + (lane & 7);
        bf_b[gp] = (uint32_t)ASTG_B
                 + sw128((uint32_t)(nrow * 128 + (((lane >> 3) & 1) * 16)));
    }
    uint32_t aoff0 = sw128((uint32_t)(r0 * 128 + ch * 16));
    // W chunk offsets: independent of tile (j0 folded into base pointer)
    uint32_t woff[8];
    #pragma unroll
    for (int i = 0; i < 8; i++) {
        int nrow = r0 + 16 * i;
        int g = nrow >> 5, c = nrow & 31;
        woff[i] = (uint32_t)(((size_t)g * HDIM + c) * KTOT * 2 + ch * 16);
    }
    int lq = lane & 3, lr = lane >> 2;

    // issue stage 0 (x + W only; k0 = q*BK <= 192 < 256) for tile tk2
    auto issue_stage0 = [&](int tk2) {
        int t2   = tk2 / TPS;
        int rem2 = tk2 - t2 * TPS;
        int m02  = (rem2 / JT) * 64;
        int j02  = (rem2 - (rem2 / JT) * JT) * 32;
        int k0   = (tk2 & 3) * BK;
        const char* xb = (const char*)(g_X + ((size_t)t2 * BATCH + m02) * 256
                                       + (size_t)r0 * 256 + ch * 8) + (size_t)k0 * 2;
        #pragma unroll
        for (int i = 0; i < 4; i++)
            cp16(sb + aoff0 + (uint32_t)(i * 2048), xb + (size_t)i * 8192);
        const char* wb = (const char*)(g_W + (size_t)j02 * KTOT) + (size_t)k0 * 2;
        uint32_t bB = sb + ASTG_B + aoff0;
        #pragma unroll
        for (int i = 0; i < 8; i++)
            cp16(bB + (uint32_t)(i * 2048), wb + woff[i]);
    };

    if (tid == 0) __stcg(mytk, atomicAdd(&g_ticket, 1));
    __syncthreads();
    int tk = __ldcg(mytk);
    if (tk < TOT) {
        issue_stage0(tk);
        asm volatile("cp.async.commit_group;" ::: "memory");
    }

    while (tk < TOT) {
        int t   = tk / TPS;
        int rem = tk - t * TPS;
        int mi  = rem / JT;
        int jj  = rem - mi * JT;
        int m0 = mi * 64, j0 = jj * 32;
        int koff = tk & 3;

        // dependency: all 60 j-tiles of (t-1, mi) complete (h RAW + ping-pong WAR + c)
        if (t > 0) {
            if (tid == 0) {
                const int* cp = &g_cnt[(t - 1) * MT + mi];
                while (ld_acq(cp) < JT) __nanosleep(32);
            }
            __syncthreads();
        }

        // stage c tile (64 rows x 32 f32 = 8KB) into CBUF as its own group.
        // Lands during mainloop iter 0's wait_group; read by epilogue via LDS.
        {
            const char* cg = (const char*)(g_C + (size_t)(m0 + r0) * HDIM + j0) + ch * 16;
            #pragma unroll
            for (int i = 0; i < 4; i++)
                cp16(sb + CBUF_OFF + (uint32_t)(r0 * 128 + ch * 16 + i * 2048),
                     cg + (size_t)i * 16 * HDIM * 4);
            asm volatile("cp.async.commit_group;" ::: "memory");
        }

        const __nv_bfloat16* hsrc = (t & 1) ? g_H1 : g_H0;
        __nv_bfloat16*       hdst = (t & 1) ? g_H0 : g_H1;
        const char* axp0 = (const char*)(g_X + ((size_t)t * BATCH + m0) * 256
                                         + (size_t)r0 * 256 + ch * 8);          // +8192*i
        const char* ahp0 = (const char*)(hsrc + (size_t)m0 * HDIM
                                         + (size_t)r0 * HDIM + ch * 8);         // +61440*i
        const char* wj = (const char*)(g_W + (size_t)j0 * KTOT);

        float acc[4][4][4];
        #pragma unroll
        for (int a = 0; a < 4; a++)
            #pragma unroll
            for (int b = 0; b < 4; b++)
                #pragma unroll
                for (int d = 0; d < 4; d++) acc[a][b][d] = 0.f;

        auto kof = [&](int it) {
            int k = it + koff;
            if (k >= NIT) k -= NIT;
            return k * BK;
        };
        auto issue_loads = [&](uint32_t stgB, int k0) {
            size_t kb = (size_t)k0 * 2;
            bool useH = (k0 >= 256);
            size_t kbh = (size_t)(k0 - 256) * 2;
            #pragma unroll
            for (int i = 0; i < 4; i++) {
                const char* ap = useH ? (ahp0 + kbh + (size_t)i * 61440)
                                      : (axp0 + kb + (size_t)i * 8192);
                cp16(stgB + aoff0 + (uint32_t)(i * 2048), ap);
            }
            uint32_t bB = stgB + ASTG_B + aoff0;
            #pragma unroll
            for (int i = 0; i < 8; i++)
                cp16(bB + (uint32_t)(i * 2048), wj + woff[i] + kb);
        };

        // mainloop: stage 0 already in flight (issued during previous epilogue)
        #pragma unroll 2
        for (int it = 0; it < NIT; it++) {
            __syncthreads();
            int pf = it + 1;
            if (pf < NIT) issue_loads(sb + (pf & 1) * STG_B, kof(pf));
            asm volatile("cp.async.commit_group;" ::: "memory");
            asm volatile("cp.async.wait_group 1;" ::: "memory");
            __syncthreads();

            uint32_t aB = sb + (it & 1) * STG_B;
            #pragma unroll
            for (int kk = 0; kk < 4; kk++) {
                uint32_t kx = (uint32_t)(kk * 32);
                uint32_t af[4][4];
                #pragma unroll
                for (int mt = 0; mt < 4; mt++) ldsm_x4(af[mt], aB + (af_b[mt] ^ kx));
                #pragma unroll
                for (int gp = 0; gp < 2; gp++) {
                    uint32_t bf[4];
                    ldsm_x4(bf, aB + (bf_b[gp] ^ kx));
                    #pragma unroll
                    for (int mt = 0; mt < 4; mt++) {
                        mma16816(acc[mt][2 * gp + 0], af[mt], &bf[0]);
                        mma16816(acc[mt][2 * gp + 1], af[mt], &bf[2]);
                    }
                }
            }
        }

        // all warps past iter-33 barrier -> buffer 0 free; grab + prefetch next tile
        __syncthreads();
        if (tid == 0) __stcg(mytk, atomicAdd(&g_ticket, 1));
        __syncthreads();
        int ntk = __ldcg(mytk);
        if (ntk < TOT) {
            issue_stage0(ntk);     // x + W only: no dependency needed
            asm volatile("cp.async.commit_group;" ::: "memory");
        }

        // ---- fused LSTM cell epilogue (tanh.approx; c from smem CBUF) ----
        float bias[4][2];
        #pragma unroll
        for (int g = 0; g < 4; g++)
            #pragma unroll
            for (int cc = 0; cc < 2; cc++)
                bias[g][cc] = g_B[g * HDIM + j0 + wn * 8 + lq * 2 + cc];

        const float* cbuf = (const float*)(smem + CBUF_OFF);
        #pragma unroll
        for (int mt = 0; mt < 4; mt++)
            #pragma unroll
            for (int rh = 0; rh < 2; rh++) {
                int rloc = mt * 16 + lr + rh * 8;
                int row = m0 + rloc;
                size_t base = (size_t)row * HDIM + j0;
                int chn = wn * 8 + lq * 2;
                float2 cold = *(const float2*)(cbuf + rloc * 32 + chn);
                float cn[2], hn[2];
                #pragma unroll
                for (int cc = 0; cc < 2; cc++) {
                    int fi = rh * 2 + cc;
                    float iv = sigm_fa(acc[mt][0][fi] + bias[0][cc]);
                    float fv = sigm_fa(acc[mt][1][fi] + bias[1][cc]);
                    float gv = tanh_fa(acc[mt][2][fi] + bias[2][cc]);
                    float ov = sigm_fa(acc[mt][3][fi] + bias[3][cc]);
                    float co = cc ? cold.y : cold.x;
                    cn[cc] = fv * co + iv * gv;
                    hn[cc] = ov * tanh_fa(cn[cc]);
                }
                __stcg((float2*)(g_C + base + chn), make_float2(cn[0], cn[1]));
                __nv_bfloat162 hv;
                hv.x = __float2bfloat16(hn[0]);
                hv.y = __float2bfloat16(hn[1]);
                *(__nv_bfloat162*)(hdst + base + chn) = hv;
            }

        __syncthreads();           // all threads' h/c writes issued + CBUF reads done
        if (tid == 0) {
            __threadfence();       // publish h/c before counting
            atomicAdd(&g_cnt[t * MT + mi], 1);
        }
        tk = ntk;
    }
}

// ---------------- final: windowed einsum + max + log-softmax ----------------
__global__ void k_final(const int* __restrict__ in2, const float* __restrict__ emb,
                        const float* __restrict__ lw, const float* __restrict__ lb,
                        float* __restrict__ out) {
    int b = blockIdx.x;
    __shared__ __align__(16) float se[NTOK2 * 128];
    __shared__ __align__(16) float shv[HDIM];
    __shared__ float sd[300];
    __shared__ float sred[4];
    int tid = threadIdx.x;  // 128 threads

    for (int i = tid; i < NTOK2 * 128; i += 128) {
        int n = i >> 7, e = i & 127;
        se[i] = emb[(size_t)in2[b * NTOK2 + n] * EDIM + e];
    }
    for (int i = tid; i < HDIM; i += 128)
        shv[i] = __bfloat162float(g_H1[(size_t)b * HDIM + i]);
    __syncthreads();

    for (int p = tid; p < 300; p += 128) {       // dotE[m][tok], m<15, tok<20
        int m = p / 20, n = p % 20;
        const float4* hv = (const float4*)(shv + m * 128);
        const float4* ev = (const float4*)(se + n * 128);
        float accv = 0.f;
        #pragma unroll
        for (int e = 0; e < 32; e++) {
            float4 a = hv[e], c = ev[e];
            accv = fmaf(a.x, c.x, fmaf(a.y, c.y, fmaf(a.z, c.z, fmaf(a.w, c.w, accv))));
        }
        sd[p] = accv;
    }
    __syncthreads();

    float mx = -3.4e38f;
    for (int p = tid; p < 90; p += 128) {
        int k = p / 18, n = p % 18;
        float rs = sd[(3 * k) * 20 + n] + sd[(3 * k + 1) * 20 + n + 1]
                 + sd[(3 * k + 2) * 20 + n + 2];
        mx = fmaxf(mx, rs);
    }
    #pragma unroll
    for (int o = 16; o > 0; o >>= 1) mx = fmaxf(mx, __shfl_xor_sync(0xffffffffu, mx, o));
    if ((tid & 31) == 0) sred[tid >> 5] = mx;
    __syncthreads();
    if (tid == 0) {
        float ms = fmaxf(fmaxf(sred[0], sred[1]), fmaxf(sred[2], sred[3]));
        float l0 = ms * lw[0] + lb[0];
        float l1 = ms * lw[1] + lb[1];
        float m2 = fmaxf(l0, l1);
        float lse = m2 + logf(expf(l0 - m2) + expf(l1 - m2));
        out[b * 2 + 0] = l0 - lse;
        out[b * 2 + 1] = l1 - lse;
    }
}

// ---------------- launch ----------------
extern "C" void kernel_launch(void* const* d_in, const int* in_sizes, int n_in,
                              void* d_out, int out_size) {
    (void)in_sizes; (void)n_in; (void)out_size;
    const int*   input1 = (const int*)  d_in[0];
    const int*   input2 = (const int*)  d_in[1];
    const float* emb    = (const float*)d_in[2];
    const float* pos    = (const float*)d_in[3];
    const float* W_ih   = (const float*)d_in[4];
    const float* W_hh   = (const float*)d_in[5];
    const float* b_ih   = (const float*)d_in[6];
    const float* b_hh   = (const float*)d_in[7];
    const float* lin_w  = (const float*)d_in[8];
    const float* lin_b  = (const float*)d_in[9];
    float* out = (float*)d_out;

    cudaFuncSetAttribute(k_lstm, cudaFuncAttributeMaxDynamicSharedMemorySize, SMEM_BYTES);

    k_prep_w<<<2048, 256>>>(W_ih, W_hh);
    k_prep_x<<<2048, 256>>>(input1, emb, pos);
    k_init<<<2048, 256>>>(b_ih, b_hh);

    // persistent grid: 4 CTAs/SM resident on 148-152 SMs; extras exit instantly
    k_lstm<<<NCTA, 128, SMEM_BYTES>>>();

    k_final<<<BATCH, 128>>>(input2, emb, lin_w, lin_b, out);
}